// round 16
// baseline (speedup 1.0000x reference)
#include <cuda_runtime.h>
#include <math_constants.h>

#define B_ 8
#define N_ 2048
#define C_ 64
#define K_ 32
#define W_COLS 67   // C + 3
#define FULL 0xffffffffu
typedef unsigned long long u64;

// Scratch (allocation-free rule: device globals)
__device__ __align__(16) float g_Gt[B_*N_*C_];     // (b, n, o)
__device__ int g_idx[B_*N_*K_];
__device__ __align__(16) float4 g_relw[B_*N_*K_];  // (rx, ry, rz, w)
__device__ __align__(16) float4 g_sC[B_*N_];       // x-sorted (x,y,z,sq)
__device__ int g_sI[B_*N_];                        // sorted -> original idx

// ---------------------------------------------------------------------------
// Kernel S: rank-scatter sort by x. key = (x_bits<<32)|idx (x>=0 => IEEE bit
// order == float order; index tie-break built in).
// ---------------------------------------------------------------------------
__global__ __launch_bounds__(512) void kS(const float* __restrict__ coords) {
    __shared__ __align__(16) u64 sk[N_];   // 16 KB of keys
    int b  = blockIdx.x >> 4;                 // 16 blocks per batch
    int p0 = (blockIdx.x & 15) << 7;          // 128 points per block
    int t  = threadIdx.x;

    for (int x = t; x < N_; x += 512) {
        unsigned bits = __float_as_uint(coords[(b*N_ + x)*3]);
        sk[x] = ((u64)bits << 32) | (unsigned)x;
    }
    __syncthreads();

    int gp = t >> 3;                          // group (2 points) id, 0..63
    int g  = t & 7;                           // lane within group
    int i0 = p0 + gp*2, i1 = i0 + 1;
    u64 k0 = sk[i0], k1 = sk[i1];
    const ulonglong2* sk2 = (const ulonglong2*)sk;
    int r0 = 0, r1 = 0;
    #pragma unroll 8
    for (int it = 0; it < N_/16; it++) {
        ulonglong2 kk = sk2[it*8 + g];        // 2 candidate keys
        r0 += (kk.x < k0) + (kk.y < k0);
        r1 += (kk.x < k1) + (kk.y < k1);
    }
    r0 += __shfl_xor_sync(FULL, r0, 1);
    r0 += __shfl_xor_sync(FULL, r0, 2);
    r0 += __shfl_xor_sync(FULL, r0, 4);
    r1 += __shfl_xor_sync(FULL, r1, 1);
    r1 += __shfl_xor_sync(FULL, r1, 2);
    r1 += __shfl_xor_sync(FULL, r1, 4);

    if (g == 0) {
        #pragma unroll
        for (int e = 0; e < 2; e++) {
            int i = e ? i1 : i0;
            int rank = e ? r1 : r0;
            const float* c = coords + (b*N_ + i)*3;
            float cx = c[0], cy = c[1], cz = c[2];
            float sq = __fadd_rn(__fadd_rn(__fmul_rn(cx,cx), __fmul_rn(cy,cy)),
                                 __fmul_rn(cz,cz));
            g_sC[b*N_ + rank] = make_float4(cx, cy, cz, sq);
            g_sI[b*N_ + rank] = i;
        }
    }
}

// ---------------------------------------------------------------------------
// Fused kernel AB: blocks [0,128) = Gt precompute, blocks [128,1152) = kNN
// (x-window culled, 2-pass) + rel/density-weight tail.
// kB distance REPLICATES the reference cdist rounding exactly:
//   sq  = ((x*x + y*y) + z*z)           (plain mul/add)
//   dot = fma(z,z', fma(y,y', x*x'))    (ascending fma chain)
//   d2  = max((sq_i + sq_j) - 2*dot, 0) (2*dot exact => fused fma == sub)
// Selection: top-32 by packed (d2_bits, orig_idx) u64 key (== stable top_k).
// Pass 1 scans only the 512 x-nearest (32 disjoint lane-sets of 16): same
// vol-per-point as 1024/32 => statistically equal md0 at half the cost;
// bound remains provably correct (32 disjoint sets => >=32 elems <= md0).
// ---------------------------------------------------------------------------
#define KA_BLOCKS 128
__global__ __launch_bounds__(512, 2) void kAB(const float* __restrict__ coords,
                                              const float* __restrict__ feats,
                                              const float* __restrict__ conv_w,
                                              const float* __restrict__ gamma,
                                              const float* __restrict__ var) {
    __shared__ __align__(16) float sbuf[12288];   // 48 KB
    int bid = blockIdx.x;
    int t = threadIdx.x;

    if (bid < KA_BLOCKS) {
        // ---------------- kA path
        float (*sW)[C_]  = (float(*)[C_])sbuf;            // [c][o] 16KB
        float (*sF)[128] = (float(*)[128])(sbuf + 4096);  // [c][n] 32KB
        int b  = bid >> 4;
        int n0 = (bid & 15) * 128;

        for (int x = t; x < C_*C_; x += 512) {
            int o = x & 63, c = x >> 6;
            float inv = gamma[o] * rsqrtf(var[o] + 1e-5f);
            sW[c][o] = conv_w[o*W_COLS + 3 + c] * inv;
        }
        for (int x = t; x < C_*128; x += 512) {
            int c = x >> 7, n = x & 127;
            sF[c][n] = feats[(b*C_ + c)*N_ + n0 + n];
        }
        __syncthreads();

        int oT = (t & 15) * 4;
        int nT = (t >> 4) * 4;
        float acc[4][4] = {};
        #pragma unroll 8
        for (int c = 0; c < C_; c++) {
            float w0 = sW[c][oT+0], w1 = sW[c][oT+1], w2 = sW[c][oT+2], w3 = sW[c][oT+3];
            #pragma unroll
            for (int j = 0; j < 4; j++) {
                float f = sF[c][nT+j];
                acc[j][0] = fmaf(w0, f, acc[j][0]);
                acc[j][1] = fmaf(w1, f, acc[j][1]);
                acc[j][2] = fmaf(w2, f, acc[j][2]);
                acc[j][3] = fmaf(w3, f, acc[j][3]);
            }
        }
        #pragma unroll
        for (int j = 0; j < 4; j++) {
            float4 v4 = make_float4(acc[j][0], acc[j][1], acc[j][2], acc[j][3]);
            *reinterpret_cast<float4*>(&g_Gt[((b*N_) + n0 + nT + j)*C_ + oT]) = v4;
        }
        return;
    }

    // ---------------- kB path: exact kNN + rel + density, warp per query
    {
        float4* sC  = (float4*)sbuf;                          // [0,8192)  32KB
        int*    sIx = (int*)(sbuf + 8192);                    // [8192,10240) 8KB
        float4 (*sRel)[K_] = (float4(*)[K_])(sbuf + 10240);   // 8KB
        int kb = bid - KA_BLOCKS;
        int warp = t >> 5, lane = t & 31;
        int b = kb >> 7;
        int i = ((kb & 127) << 4) + warp;      // original query index

        for (int x = t; x < N_; x += 512) {
            sC[x]  = g_sC[b*N_ + x];
            sIx[x] = g_sI[b*N_ + x];
        }
        __syncthreads();

        const float* qc = coords + (b*N_ + i)*3;
        float4 q;
        q.x = qc[0]; q.y = qc[1]; q.z = qc[2];
        q.w = __fadd_rn(__fadd_rn(__fmul_rn(q.x,q.x), __fmul_rn(q.y,q.y)),
                        __fmul_rn(q.z,q.z));

        auto refd2 = [&](const float4& p) -> float {
            float dot = __fmaf_rn(q.z, p.z, __fmaf_rn(q.y, p.y, __fmul_rn(q.x, p.x)));
            float d2  = __fmaf_rn(-2.0f, dot, __fadd_rn(q.w, p.w));
            return fmaxf(d2, 0.0f);
        };
        auto lower_x = [&](float a) -> int {    // first idx with x >= a
            int lo = 0, hi = N_;
            while (lo < hi) { int m2 = (lo+hi) >> 1; if (sC[m2].x < a) lo = m2+1; else hi = m2; }
            return lo;
        };
        auto upper_x = [&](float a) -> int {    // first idx with x > a
            int lo = 0, hi = N_;
            while (lo < hi) { int m2 = (lo+hi) >> 1; if (sC[m2].x <= a) lo = m2+1; else hi = m2; }
            return lo;
        };

        // ---- Pass 1: provable upper bound md0 on 32nd smallest refd2,
        // from the 512 x-nearest points (32 disjoint lane-sets of 16).
        int p = lower_x(q.x);
        int w0 = p - 256;
        w0 = w0 < 0 ? 0 : (w0 > N_-512 ? N_-512 : w0);
        w0 &= ~31;
        float lmin = CUDART_INF_F;
        #pragma unroll 4
        for (int it = 0; it < 16; it++)
            lmin = fminf(lmin, refd2(sC[w0 + it*32 + lane]));
        float md0 = lmin;
        #pragma unroll
        for (int off = 16; off; off >>= 1)
            md0 = fmaxf(md0, __shfl_xor_sync(FULL, md0, off));

        // ---- x-window: points outside cannot be in top-32 (margin >> fp err)
        float s = sqrtf(md0) + 1e-3f;
        int tstart = lower_x(q.x - s) & ~31;
        int hi0 = upper_x(q.x + s);
        int tend = (hi0 + 31) & ~31;
        if (tend > N_) tend = N_;

        // ---- Init: first window tile, bitonic-sorted by packed key
        u64 bkey;
        {
            int jj = tstart + lane;
            float d2 = refd2(sC[jj]);
            bkey = ((u64)__float_as_uint(d2) << 32) | (unsigned)sIx[jj];
        }
        #pragma unroll
        for (int k = 2; k <= 32; k <<= 1) {
            #pragma unroll
            for (int j = k >> 1; j > 0; j >>= 1) {
                u64 ok = __shfl_xor_sync(FULL, bkey, j);
                bool up       = ((lane & k) == 0);
                bool keep_min = (((lane & j) == 0) == up);
                bool less     = ok < bkey;
                if (keep_min == less) bkey = ok;   // keys unique
            }
        }
        u64 mkey = __shfl_sync(FULL, bkey, 31);    // current worst

        // ---- Pass 2: windowed scan + sorted-lane insertion (no per-insert
        // staleness logic: inserting a key >= set-worst is a natural no-op)
        for (int tt = tstart + 32; tt < tend; tt += 32) {
            int jj = tt + lane;
            float d2 = refd2(sC[jj]);
            u64 key = ((u64)__float_as_uint(d2) << 32) | (unsigned)sIx[jj];
            unsigned m = __ballot_sync(FULL, (d2 <= md0) && (key < mkey));
            if (!m) continue;
            while (m) {   // warp-uniform serial insertion
                int src = __ffs(m) - 1;
                m &= m - 1;
                u64 ck = __shfl_sync(FULL, key, src);
                u64 pk = __shfl_up_sync(FULL, bkey, 1);
                bool gt_self = bkey > ck;
                bool gt_prev = (lane > 0) && (pk > ck);
                if (gt_self) bkey = gt_prev ? pk : ck;
            }
            mkey = __shfl_sync(FULL, bkey, 31);    // refresh once per tile
        }
        int bi = (int)(bkey & 0xffffffffu);        // original neighbor index

        // ---- Tail: rel coords + density weight
        const float* gc = coords + (b*N_ + bi)*3;
        float rx = (gc[0] - q.x) / 0.2f;
        float ry = (gc[1] - q.y) / 0.2f;
        float rz = (gc[2] - q.z) / 0.2f;
        sRel[warp][lane] = make_float4(rx, ry, rz, 0.f);
        __syncwarp();

        float v[K_];
        #pragma unroll
        for (int j = 0; j < K_; j++) {
            float4 o = sRel[warp][j];              // LDS.128 broadcast
            float dx = o.x - rx, dy = o.y - ry, dz = o.z - rz;
            float d = dx*dx + dy*dy + dz*dz;
            v[j] = (j == lane) ? CUDART_INF_F : d;
        }
        #pragma unroll
        for (int h = 0; h < 2; h++) {
            const int base = h * 16;
            #pragma unroll
            for (int k = 2; k <= 16; k <<= 1) {
                #pragma unroll
                for (int j = k >> 1; j > 0; j >>= 1) {
                    #pragma unroll
                    for (int ii = 0; ii < 16; ii++) {
                        int ll = ii ^ j;
                        if (ll > ii) {
                            float a = v[base+ii], c = v[base+ll];
                            float lo = fminf(a, c), hi = fmaxf(a, c);
                            if ((ii & k) == 0) { v[base+ii] = lo; v[base+ll] = hi; }
                            else               { v[base+ii] = hi; v[base+ll] = lo; }
                        }
                    }
                }
            }
        }
        float kd = fminf(v[0], v[31]);             // 16th smallest of union
        #pragma unroll
        for (int ii = 1; ii < 16; ii++)
            kd = fmaxf(kd, fminf(v[ii], v[31-ii]));

        float kth = sqrtf(kd) * 0.2f;
        float raw = fmaxf(kth, 1e-8f);
        raw = raw * raw * raw;
        float sum = raw;
        #pragma unroll
        for (int off = 16; off; off >>= 1) sum += __shfl_xor_sync(FULL, sum, off);
        float w = raw / fmaxf(sum, 1e-8f);

        int gi = (b*N_ + i)*K_ + lane;
        g_relw[gi] = make_float4(rx, ry, rz, w);
        g_idx[gi] = bi;
    }
}

// ---------------------------------------------------------------------------
// Kernel C: warp-per-point, processed in X-SORTED order (Gt gather L1 reuse),
// float2 channel pairs (o = 2*lane, 2*lane+1).
//   out[o,i] = sum_k w_k * relu(Gt[idx_k][o] + Wrel'[o]·rel_k + bias'[o])
// ---------------------------------------------------------------------------
__global__ __launch_bounds__(256) void kC(const float* __restrict__ conv_w,
                                          const float* __restrict__ gamma,
                                          const float* __restrict__ beta,
                                          const float* __restrict__ mean,
                                          const float* __restrict__ var,
                                          float* __restrict__ out) {
    __shared__ __align__(16) float4 sRel[8][K_];
    __shared__ int sJn[8][K_];
    int t = threadIdx.x;
    int warp = t >> 5, lane = t & 31;
    int spos = blockIdx.x * 8 + warp;      // sorted slot (b*N + pos)
    int b = spos >> 11;
    int i = g_sI[spos];                    // original point index
    int pidx = b*N_ + i;

    int o0 = 2*lane, o1 = 2*lane + 1;
    float inv0 = gamma[o0] * rsqrtf(var[o0] + 1e-5f);
    float inv1 = gamma[o1] * rsqrtf(var[o1] + 1e-5f);
    float w0x = conv_w[o0*W_COLS+0]*inv0, w0y = conv_w[o0*W_COLS+1]*inv0, w0z = conv_w[o0*W_COLS+2]*inv0;
    float w1x = conv_w[o1*W_COLS+0]*inv1, w1y = conv_w[o1*W_COLS+1]*inv1, w1z = conv_w[o1*W_COLS+2]*inv1;
    float bb0 = beta[o0] - mean[o0]*inv0;
    float bb1 = beta[o1] - mean[o1]*inv1;

    sRel[warp][lane] = g_relw[pidx*K_ + lane];
    sJn[warp][lane]  = g_idx[pidx*K_ + lane];
    __syncwarp();

    const float* Gb = g_Gt + (b*N_)*C_;
    float acc0 = 0.f, acc1 = 0.f;
    #pragma unroll 4
    for (int k = 0; k < K_; k++) {
        float4 r4 = sRel[warp][k];
        int    jn = sJn[warp][k];
        float2 g01 = *reinterpret_cast<const float2*>(&Gb[jn*C_ + o0]);
        float v0 = fmaf(w0z, r4.z, fmaf(w0y, r4.y, fmaf(w0x, r4.x, g01.x + bb0)));
        float v1 = fmaf(w1z, r4.z, fmaf(w1y, r4.y, fmaf(w1x, r4.x, g01.y + bb1)));
        v0 = fmaxf(v0, 0.f);
        v1 = fmaxf(v1, 0.f);
        acc0 = fmaf(r4.w, v0, acc0);
        acc1 = fmaf(r4.w, v1, acc1);
    }
    out[(b*C_ + o0)*N_ + i] = acc0;
    out[(b*C_ + o1)*N_ + i] = acc1;
}

extern "C" void kernel_launch(void* const* d_in, const int* in_sizes, int n_in,
                              void* d_out, int out_size) {
    const float* coords = (const float*)d_in[0];
    const float* feats  = (const float*)d_in[1];
    const float* conv_w = (const float*)d_in[2];
    const float* gamma  = (const float*)d_in[3];
    const float* beta   = (const float*)d_in[4];
    const float* mean   = (const float*)d_in[5];
    const float* var    = (const float*)d_in[6];
    float* out = (float*)d_out;

    kS<<<B_*16, 512>>>(coords);
    kAB<<<KA_BLOCKS + B_*N_/16, 512>>>(coords, feats, conv_w, gamma, var);
    kC<<<B_*N_/8, 256>>>(conv_w, gamma, beta, mean, var, out);
}

// round 17
// speedup vs baseline: 1.1140x; 1.1140x over previous
#include <cuda_runtime.h>
#include <math_constants.h>

#define B_ 8
#define N_ 2048
#define C_ 64
#define K_ 32
#define W_COLS 67   // C + 3
#define FULL 0xffffffffu
typedef unsigned long long u64;

// Scratch (allocation-free rule: device globals)
__device__ __align__(16) float g_Gt[B_*N_*C_];     // (b, n, o)
__device__ int g_idx[B_*N_*K_];
__device__ __align__(16) float4 g_relw[B_*N_*K_];  // (rx, ry, rz, w)
__device__ __align__(16) float4 g_sC[B_*N_];       // x-sorted (x,y,z,sq)
__device__ int g_sI[B_*N_];                        // sorted -> original idx

// ---------------------------------------------------------------------------
// Kernel S: rank-scatter sort by x. key = (x_bits<<32)|idx (x>=0 => IEEE bit
// order == float order; index tie-break built in). Register-tiled (2 points
// per group, 8 threads per point).
// ---------------------------------------------------------------------------
__global__ __launch_bounds__(512) void kS(const float* __restrict__ coords) {
    __shared__ __align__(16) u64 sk[N_];   // 16 KB of keys
    int b  = blockIdx.x >> 4;                 // 16 blocks per batch
    int p0 = (blockIdx.x & 15) << 7;          // 128 points per block
    int t  = threadIdx.x;

    for (int x = t; x < N_; x += 512) {
        unsigned bits = __float_as_uint(coords[(b*N_ + x)*3]);
        sk[x] = ((u64)bits << 32) | (unsigned)x;
    }
    __syncthreads();

    int gp = t >> 3;                          // group (2 points) id, 0..63
    int g  = t & 7;                           // lane within group
    int i0 = p0 + gp*2, i1 = i0 + 1;
    u64 k0 = sk[i0], k1 = sk[i1];
    const ulonglong2* sk2 = (const ulonglong2*)sk;
    int r0 = 0, r1 = 0;
    #pragma unroll 8
    for (int it = 0; it < N_/16; it++) {
        ulonglong2 kk = sk2[it*8 + g];        // 2 candidate keys
        r0 += (kk.x < k0) + (kk.y < k0);
        r1 += (kk.x < k1) + (kk.y < k1);
    }
    r0 += __shfl_xor_sync(FULL, r0, 1);
    r0 += __shfl_xor_sync(FULL, r0, 2);
    r0 += __shfl_xor_sync(FULL, r0, 4);
    r1 += __shfl_xor_sync(FULL, r1, 1);
    r1 += __shfl_xor_sync(FULL, r1, 2);
    r1 += __shfl_xor_sync(FULL, r1, 4);

    if (g == 0) {
        #pragma unroll
        for (int e = 0; e < 2; e++) {
            int i = e ? i1 : i0;
            int rank = e ? r1 : r0;
            const float* c = coords + (b*N_ + i)*3;
            float cx = c[0], cy = c[1], cz = c[2];
            float sq = __fadd_rn(__fadd_rn(__fmul_rn(cx,cx), __fmul_rn(cy,cy)),
                                 __fmul_rn(cz,cz));
            g_sC[b*N_ + rank] = make_float4(cx, cy, cz, sq);
            g_sI[b*N_ + rank] = i;
        }
    }
}

// ---------------------------------------------------------------------------
// Fused kernel AB: blocks [0,128) = Gt precompute, blocks [128,1152) = kNN
// (x-window culled, 2-pass) + rel/density-weight tail.
// kB distance REPLICATES the reference cdist rounding exactly:
//   sq  = ((x*x + y*y) + z*z)           (plain mul/add)
//   dot = fma(z,z', fma(y,y', x*x'))    (ascending fma chain)
//   d2  = max((sq_i + sq_j) - 2*dot, 0) (2*dot exact => fused fma == sub)
// Selection: top-32 by packed (d2_bits, orig_idx) u64 key (== stable top_k).
// Pass 1: champion form (1024 x-nearest, 32 disjoint lane-sets of 32).
// Pass 2: FIXED window bounds, visited CENTER-OUT (init tile = tile
// containing the query, then alternate right/left). Same candidate multiset
// => identical final top-32; order only tightens mkey sooner.
// ---------------------------------------------------------------------------
#define KA_BLOCKS 128
__global__ __launch_bounds__(512, 2) void kAB(const float* __restrict__ coords,
                                              const float* __restrict__ feats,
                                              const float* __restrict__ conv_w,
                                              const float* __restrict__ gamma,
                                              const float* __restrict__ var) {
    __shared__ __align__(16) float sbuf[12288];   // 48 KB
    int bid = blockIdx.x;
    int t = threadIdx.x;

    if (bid < KA_BLOCKS) {
        // ---------------- kA path
        float (*sW)[C_]  = (float(*)[C_])sbuf;            // [c][o] 16KB
        float (*sF)[128] = (float(*)[128])(sbuf + 4096);  // [c][n] 32KB
        int b  = bid >> 4;
        int n0 = (bid & 15) * 128;

        for (int x = t; x < C_*C_; x += 512) {
            int o = x & 63, c = x >> 6;
            float inv = gamma[o] * rsqrtf(var[o] + 1e-5f);
            sW[c][o] = conv_w[o*W_COLS + 3 + c] * inv;
        }
        for (int x = t; x < C_*128; x += 512) {
            int c = x >> 7, n = x & 127;
            sF[c][n] = feats[(b*C_ + c)*N_ + n0 + n];
        }
        __syncthreads();

        int oT = (t & 15) * 4;
        int nT = (t >> 4) * 4;
        float acc[4][4] = {};
        #pragma unroll 8
        for (int c = 0; c < C_; c++) {
            float w0 = sW[c][oT+0], w1 = sW[c][oT+1], w2 = sW[c][oT+2], w3 = sW[c][oT+3];
            #pragma unroll
            for (int j = 0; j < 4; j++) {
                float f = sF[c][nT+j];
                acc[j][0] = fmaf(w0, f, acc[j][0]);
                acc[j][1] = fmaf(w1, f, acc[j][1]);
                acc[j][2] = fmaf(w2, f, acc[j][2]);
                acc[j][3] = fmaf(w3, f, acc[j][3]);
            }
        }
        #pragma unroll
        for (int j = 0; j < 4; j++) {
            float4 v4 = make_float4(acc[j][0], acc[j][1], acc[j][2], acc[j][3]);
            *reinterpret_cast<float4*>(&g_Gt[((b*N_) + n0 + nT + j)*C_ + oT]) = v4;
        }
        return;
    }

    // ---------------- kB path: exact kNN + rel + density, warp per query
    {
        float4* sC  = (float4*)sbuf;                          // [0,8192)  32KB
        int*    sIx = (int*)(sbuf + 8192);                    // [8192,10240) 8KB
        float4 (*sRel)[K_] = (float4(*)[K_])(sbuf + 10240);   // 8KB
        int kb = bid - KA_BLOCKS;
        int warp = t >> 5, lane = t & 31;
        int b = kb >> 7;
        int i = ((kb & 127) << 4) + warp;      // original query index

        for (int x = t; x < N_; x += 512) {
            sC[x]  = g_sC[b*N_ + x];
            sIx[x] = g_sI[b*N_ + x];
        }
        __syncthreads();

        const float* qc = coords + (b*N_ + i)*3;
        float4 q;
        q.x = qc[0]; q.y = qc[1]; q.z = qc[2];
        q.w = __fadd_rn(__fadd_rn(__fmul_rn(q.x,q.x), __fmul_rn(q.y,q.y)),
                        __fmul_rn(q.z,q.z));

        auto refd2 = [&](const float4& p) -> float {
            float dot = __fmaf_rn(q.z, p.z, __fmaf_rn(q.y, p.y, __fmul_rn(q.x, p.x)));
            float d2  = __fmaf_rn(-2.0f, dot, __fadd_rn(q.w, p.w));
            return fmaxf(d2, 0.0f);
        };
        auto lower_x = [&](float a) -> int {    // first idx with x >= a
            int lo = 0, hi = N_;
            while (lo < hi) { int m2 = (lo+hi) >> 1; if (sC[m2].x < a) lo = m2+1; else hi = m2; }
            return lo;
        };
        auto upper_x = [&](float a) -> int {    // first idx with x > a
            int lo = 0, hi = N_;
            while (lo < hi) { int m2 = (lo+hi) >> 1; if (sC[m2].x <= a) lo = m2+1; else hi = m2; }
            return lo;
        };

        // ---- Pass 1: provable upper bound md0 on 32nd smallest refd2,
        // from the 1024 x-nearest points (32 disjoint lane-sets of 32).
        int p = lower_x(q.x);
        int w0 = p - 512;
        w0 = w0 < 0 ? 0 : (w0 > N_-1024 ? N_-1024 : w0);
        w0 &= ~31;
        float lmin = CUDART_INF_F;
        #pragma unroll 4
        for (int it = 0; it < 32; it++)
            lmin = fminf(lmin, refd2(sC[w0 + it*32 + lane]));
        float md0 = lmin;
        #pragma unroll
        for (int off = 16; off; off >>= 1)
            md0 = fmaxf(md0, __shfl_xor_sync(FULL, md0, off));

        // ---- x-window: points outside cannot be in top-32 (margin >> fp err)
        float s = sqrtf(md0) + 1e-3f;
        int tstart = lower_x(q.x - s) & ~31;
        int hi0 = upper_x(q.x + s);
        int tend = (hi0 + 31) & ~31;
        if (tend > N_) tend = N_;

        // ---- Init: CENTER tile (contains p), bitonic-sorted by packed key
        int cT = (p - 16) & ~31;
        cT = cT < tstart ? tstart : (cT > tend - 32 ? tend - 32 : cT);
        u64 bkey;
        {
            int jj = cT + lane;
            float d2 = refd2(sC[jj]);
            bkey = ((u64)__float_as_uint(d2) << 32) | (unsigned)sIx[jj];
        }
        #pragma unroll
        for (int k = 2; k <= 32; k <<= 1) {
            #pragma unroll
            for (int j = k >> 1; j > 0; j >>= 1) {
                u64 ok = __shfl_xor_sync(FULL, bkey, j);
                bool up       = ((lane & k) == 0);
                bool keep_min = (((lane & j) == 0) == up);
                bool less     = ok < bkey;
                if (keep_min == less) bkey = ok;   // keys unique
            }
        }
        u64 mkey = __shfl_sync(FULL, bkey, 31);    // current worst

        auto scan_tile = [&](int tt) {
            int jj = tt + lane;
            float d2 = refd2(sC[jj]);
            u64 key = ((u64)__float_as_uint(d2) << 32) | (unsigned)sIx[jj];
            unsigned m = __ballot_sync(FULL, (d2 <= md0) && (key < mkey));
            if (!m) return;
            while (m) {   // warp-uniform serial insertion
                int src = __ffs(m) - 1;
                m &= m - 1;
                u64 ck = __shfl_sync(FULL, key, src);
                u64 pk = __shfl_up_sync(FULL, bkey, 1);
                bool gt_self = bkey > ck;
                bool gt_prev = (lane > 0) && (pk > ck);
                if (gt_self) bkey = gt_prev ? pk : ck;
            }
            mkey = __shfl_sync(FULL, bkey, 31);    // refresh once per tile
        };

        // ---- Pass 2: fixed window, CENTER-OUT visit order (pure index
        // arithmetic; no per-round sqrt/LDS termination checks)
        int left = cT - 32, right = cT + 32;
        while (left >= tstart || right < tend) {
            if (right < tend)   { scan_tile(right); right += 32; }
            if (left >= tstart) { scan_tile(left);  left  -= 32; }
        }
        int bi = (int)(bkey & 0xffffffffu);        // original neighbor index

        // ---- Tail: rel coords + density weight
        const float* gc = coords + (b*N_ + bi)*3;
        float rx = (gc[0] - q.x) / 0.2f;
        float ry = (gc[1] - q.y) / 0.2f;
        float rz = (gc[2] - q.z) / 0.2f;
        sRel[warp][lane] = make_float4(rx, ry, rz, 0.f);
        __syncwarp();

        float v[K_];
        #pragma unroll
        for (int j = 0; j < K_; j++) {
            float4 o = sRel[warp][j];              // LDS.128 broadcast
            float dx = o.x - rx, dy = o.y - ry, dz = o.z - rz;
            float d = dx*dx + dy*dy + dz*dz;
            v[j] = (j == lane) ? CUDART_INF_F : d;
        }
        #pragma unroll
        for (int h = 0; h < 2; h++) {
            const int base = h * 16;
            #pragma unroll
            for (int k = 2; k <= 16; k <<= 1) {
                #pragma unroll
                for (int j = k >> 1; j > 0; j >>= 1) {
                    #pragma unroll
                    for (int ii = 0; ii < 16; ii++) {
                        int ll = ii ^ j;
                        if (ll > ii) {
                            float a = v[base+ii], c = v[base+ll];
                            float lo = fminf(a, c), hi = fmaxf(a, c);
                            if ((ii & k) == 0) { v[base+ii] = lo; v[base+ll] = hi; }
                            else               { v[base+ii] = hi; v[base+ll] = lo; }
                        }
                    }
                }
            }
        }
        float kd = fminf(v[0], v[31]);             // 16th smallest of union
        #pragma unroll
        for (int ii = 1; ii < 16; ii++)
            kd = fmaxf(kd, fminf(v[ii], v[31-ii]));

        float kth = sqrtf(kd) * 0.2f;
        float raw = fmaxf(kth, 1e-8f);
        raw = raw * raw * raw;
        float sum = raw;
        #pragma unroll
        for (int off = 16; off; off >>= 1) sum += __shfl_xor_sync(FULL, sum, off);
        float w = raw / fmaxf(sum, 1e-8f);

        int gi = (b*N_ + i)*K_ + lane;
        g_relw[gi] = make_float4(rx, ry, rz, w);
        g_idx[gi] = bi;
    }
}

// ---------------------------------------------------------------------------
// Kernel C: warp-per-point, processed in X-SORTED order (Gt gather L1 reuse).
//   out[o,i] = sum_k w_k * relu(Gt[idx_k][o] + Wrel'[o]·rel_k + bias'[o])
// ---------------------------------------------------------------------------
__global__ __launch_bounds__(256) void kC(const float* __restrict__ conv_w,
                                          const float* __restrict__ gamma,
                                          const float* __restrict__ beta,
                                          const float* __restrict__ mean,
                                          const float* __restrict__ var,
                                          float* __restrict__ out) {
    __shared__ __align__(16) float4 sRel[8][K_];
    __shared__ int sJn[8][K_];
    int t = threadIdx.x;
    int warp = t >> 5, lane = t & 31;
    int spos = blockIdx.x * 8 + warp;      // sorted slot (b*N + pos)
    int b = spos >> 11;
    int i = g_sI[spos];                    // original point index
    int pidx = b*N_ + i;

    int o0 = lane, o1 = lane + 32;
    float inv0 = gamma[o0] * rsqrtf(var[o0] + 1e-5f);
    float inv1 = gamma[o1] * rsqrtf(var[o1] + 1e-5f);
    float w0x = conv_w[o0*W_COLS+0]*inv0, w0y = conv_w[o0*W_COLS+1]*inv0, w0z = conv_w[o0*W_COLS+2]*inv0;
    float w1x = conv_w[o1*W_COLS+0]*inv1, w1y = conv_w[o1*W_COLS+1]*inv1, w1z = conv_w[o1*W_COLS+2]*inv1;
    float bb0 = beta[o0] - mean[o0]*inv0;
    float bb1 = beta[o1] - mean[o1]*inv1;

    sRel[warp][lane] = g_relw[pidx*K_ + lane];
    sJn[warp][lane]  = g_idx[pidx*K_ + lane];
    __syncwarp();

    const float* Gb = g_Gt + (b*N_)*C_;
    float acc0 = 0.f, acc1 = 0.f;
    #pragma unroll 4
    for (int k = 0; k < K_; k++) {
        float4 r4 = sRel[warp][k];
        int    jn = sJn[warp][k];
        float g0 = Gb[jn*C_ + o0];
        float g1 = Gb[jn*C_ + o1];
        float v0 = fmaf(w0z, r4.z, fmaf(w0y, r4.y, fmaf(w0x, r4.x, g0 + bb0)));
        float v1 = fmaf(w1z, r4.z, fmaf(w1y, r4.y, fmaf(w1x, r4.x, g1 + bb1)));
        v0 = fmaxf(v0, 0.f);
        v1 = fmaxf(v1, 0.f);
        acc0 = fmaf(r4.w, v0, acc0);
        acc1 = fmaf(r4.w, v1, acc1);
    }
    out[(b*C_ + o0)*N_ + i] = acc0;
    out[(b*C_ + o1)*N_ + i] = acc1;
}

extern "C" void kernel_launch(void* const* d_in, const int* in_sizes, int n_in,
                              void* d_out, int out_size) {
    const float* coords = (const float*)d_in[0];
    const float* feats  = (const float*)d_in[1];
    const float* conv_w = (const float*)d_in[2];
    const float* gamma  = (const float*)d_in[3];
    const float* beta   = (const float*)d_in[4];
    const float* mean   = (const float*)d_in[5];
    const float* var    = (const float*)d_in[6];
    float* out = (float*)d_out;

    kS<<<B_*16, 512>>>(coords);
    kAB<<<KA_BLOCKS + B_*N_/16, 512>>>(coords, feats, conv_w, gamma, var);
    kC<<<B_*N_/8, 256>>>(conv_w, gamma, beta, mean, var, out);
}